// round 16
// baseline (speedup 1.0000x reference)
#include <cuda_runtime.h>
#include <cuda_fp16.h>
#include <cstdint>

// ---------------- problem constants ----------------
#define NROWS  10000
#define MPAD   10240           // 80*128
#define NHID   128
#define NFEAT  512
#define KPAD   10112           // 158*64, 79*128
#define BKC    64
#define NCHUNK (KPAD / BKC)    // 158
#define Z2 11                  // gemm2 K-split
#define Z4 4                   // gemm4 K-split
#define TC_SMEM 147456         // 3 stages x 48KB (template variants)
// fused gemm2: A32 ring 3x32KB + A16 2x16KB + B ring 3x16KB
#define F_SMEM  180224

// ---------------- scratch (__device__ globals; no allocs) ----------------
__device__ __align__(256) __half g_part[(size_t)Z4 * MPAD * NFEAT];  // fp16 partials (>= Z2*MPAD*NHID)
__device__ __align__(256) __half g_adj_h[(size_t)MPAD * KPAD];       // round16(adj), written by gemm2_fused
__device__ __align__(256) __half g_xh[(size_t)KPAD * NFEAT];         // round16(x), padded rows
__device__ __align__(256) __half g_W1t_hi[NHID * NFEAT];
__device__ __align__(256) __half g_W1t_lo[NHID * NFEAT];
__device__ __align__(256) __half g_T1t[(size_t)NHID * KPAD];         // [NHID, KPAD]
__device__ __align__(256) __half g_Hh [(size_t)MPAD * NHID];         // H fp16 [MPAD, NHID]
__device__ __align__(256) __half g_W2t_hi[NFEAT * NHID];
__device__ __align__(256) __half g_W2t_lo[NFEAT * NHID];
__device__ __align__(256) __half g_T2t[(size_t)NFEAT * KPAD];        // T2^T fp16 [NFEAT, KPAD]

// ---------------- PTX helpers (legal on bare sm_103) ----------------
__device__ __forceinline__ uint32_t smem_u32(const void* p) {
    uint32_t a;
    asm("{ .reg .u64 t; cvta.to.shared.u64 t, %1; cvt.u32.u64 %0, t; }" : "=r"(a) : "l"(p));
    return a;
}
__device__ __forceinline__ uint32_t swz(uint32_t off) {
    return off ^ ((off >> 3) & 0x70);
}
__device__ __forceinline__ void cp_async16(uint32_t dst, const void* src) {
    asm volatile("cp.async.cg.shared.global [%0], [%1], 16;" :: "r"(dst), "l"(src));
}
__device__ __forceinline__ void cp_async16_zfill(uint32_t dst, const void* src, uint32_t srcbytes) {
    asm volatile("cp.async.cg.shared.global [%0], [%1], 16, %2;"
                 :: "r"(dst), "l"(src), "r"(srcbytes));
}
__device__ __forceinline__ void cp_commit() {
    asm volatile("cp.async.commit_group;" ::: "memory");
}
template <int N>
__device__ __forceinline__ void cp_wait() {
    asm volatile("cp.async.wait_group %0;" :: "n"(N) : "memory");
}
__device__ __forceinline__ void ldsm4(uint32_t* r, uint32_t addr) {
    asm volatile("ldmatrix.sync.aligned.m8n8.x4.shared.b16 {%0,%1,%2,%3}, [%4];"
                 : "=r"(r[0]), "=r"(r[1]), "=r"(r[2]), "=r"(r[3]) : "r"(addr));
}
__device__ __forceinline__ void mma_f16(float* d, const uint32_t* a,
                                        uint32_t b0, uint32_t b1) {
    asm volatile(
        "mma.sync.aligned.m16n8k16.row.col.f32.f16.f16.f32 "
        "{%0,%1,%2,%3}, {%4,%5,%6,%7}, {%8,%9}, {%0,%1,%2,%3};"
        : "+f"(d[0]), "+f"(d[1]), "+f"(d[2]), "+f"(d[3])
        : "r"(a[0]), "r"(a[1]), "r"(a[2]), "r"(a[3]), "r"(b0), "r"(b1));
}

// ================= fused gemm2: reads fp32 adj, emits fp16 adj + partials =================
// part[z][m][n] = sum_{k in z} round16(adj)[m][k] * T1t[n][k];  also Ah[m][k] = round16(adj).
// CTA 128x128, 16 warps (4x4), warp tile 32x32, BKC=64.
// A: cp.async fp32 ring (3x32KB, zfill OOB) -> LDS convert -> fp16 STS (2x16KB) + STG.
// B: cp.async 3-ring (3x16KB). One commit group per chunk; lookahead 2.
__global__ __launch_bounds__(512, 1)
void gemm2_fused(const float* __restrict__ adj,
                 const __half* __restrict__ Bhi,   // T1t [NHID, KPAD]
                 __half* __restrict__ Ah,          // [MPAD, KPAD]
                 __half* __restrict__ part, size_t part_stride)
{
    extern __shared__ __align__(128) char smem[];
    const uint32_t sbase = smem_u32(smem);
    const uint32_t A32b  = sbase;             // 3 x 32KB
    const uint32_t A16b  = sbase + 98304u;    // 2 x 16KB
    const uint32_t Bb    = sbase + 131072u;   // 3 x 16KB
    const int tid  = threadIdx.x;
    const int wid  = tid >> 5;
    const int lane = tid & 31;
    const int wm = wid & 3;
    const int wn = wid >> 2;
    const int m0 = blockIdx.y * 128;
    const int n0 = blockIdx.x * 128;

    const int gz = gridDim.z, bz = blockIdx.z;
    const int cbeg = (NCHUNK * bz) / gz;
    const int cend = (NCHUNK * (bz + 1)) / gz;
    part += (size_t)bz * part_stride;

    const __half* baseB = Bhi + (size_t)n0 * KPAD;

    auto load_chunk = [&](int c) {
        // A: 2048 granules of 16B fp32 (128 rows x 64 k)
        const uint32_t aslot = A32b + (uint32_t)(c % 3) * 32768u;
        const int k0 = c * 64;
#pragma unroll
        for (int j = 0; j < 4; j++) {
            const int idx = tid + j * 512;      // 0..2047
            const int row = idx >> 4;
            const int g   = idx & 15;
            const int gr  = m0 + row;
            const int gk  = k0 + g * 4;
            const bool ok = (gr < NROWS) && (gk < NROWS);   // gk%4==0, NROWS%4==0
            const float* src = ok ? (adj + (size_t)gr * NROWS + gk) : adj;
            cp_async16_zfill(aslot + (uint32_t)idx * 16u, src, ok ? 16u : 0u);
        }
        // B: 1024 granules (128 rows x 64 k fp16)
        const uint32_t bslot = Bb + (uint32_t)(c % 3) * 16384u;
        const size_t kb = (size_t)c * 128;
#pragma unroll
        for (int i = 0; i < 2; i++) {
            const int idx = tid + i * 512;
            const int r  = idx >> 3;
            const int cc = idx & 7;
            cp_async16(bslot + swz((uint32_t)(r * 128 + cc * 16)),
                       (const char*)baseB + kb + (size_t)r * (KPAD * 2) + cc * 16);
        }
        cp_commit();
    };

    const uint32_t rL   = lane & 15;
    const uint32_t cAdd = lane >> 4;
    const uint32_t aRow0 = (uint32_t)(wm * 32) + rL;
    const uint32_t bRow0 = (uint32_t)(wn * 32) + rL;
    const uint32_t kOff0 = cAdd * 16u;

    float acc[2][4][4];
#pragma unroll
    for (int i = 0; i < 2; i++)
#pragma unroll
        for (int j = 0; j < 4; j++)
#pragma unroll
            for (int k = 0; k < 4; k++) acc[i][j][k] = 0.0f;

    // prologue: lookahead 2
    load_chunk(cbeg);
    if (cbeg + 1 < cend) load_chunk(cbeg + 1);

    for (int c = cbeg; c < cend; c++) {
        if (c + 1 < cend) cp_wait<1>(); else cp_wait<0>();
        __syncthreads();                       // chunk c's A32 + B visible
        if (c + 2 < cend) load_chunk(c + 2);   // slot (c+2)%3 != c%3

        // ---- convert A: smem fp32 -> fp16 smem (swizzled) + global ----
        const uint32_t a32cur = A32b + (uint32_t)(c % 3) * 32768u;
        const uint32_t a16cur = A16b + (uint32_t)(c & 1) * 16384u;
#pragma unroll
        for (int j = 0; j < 4; j++) {
            const int idx = tid + j * 512;
            const int row = idx >> 4;
            const int g   = idx & 15;
            const float4 v = *reinterpret_cast<const float4*>(smem + (a32cur - sbase) + (size_t)idx * 16);
            __half2 p0 = __floats2half2_rn(v.x, v.y);
            __half2 p1 = __floats2half2_rn(v.z, v.w);
            const uint32_t soff = swz((uint32_t)(row * 128 + (g >> 1) * 16)) + (uint32_t)(g & 1) * 8u;
            __half2* sp = reinterpret_cast<__half2*>(smem + (a16cur - sbase) + soff);
            sp[0] = p0; sp[1] = p1;
            __half2* gp = reinterpret_cast<__half2*>(Ah + (size_t)(m0 + row) * KPAD + c * 64 + g * 4);
            gp[0] = p0; gp[1] = p1;
        }
        __syncthreads();                       // A16[c&1] visible

        const uint32_t bcur = Bb + (uint32_t)(c % 3) * 16384u;
#pragma unroll
        for (int ks = 0; ks < 4; ks++) {
            const uint32_t kb = kOff0 + (uint32_t)ks * 32u;
            uint32_t Af[2][4], Bf[2][4];
#pragma unroll
            for (int mt = 0; mt < 2; mt++)
                ldsm4(Af[mt], a16cur + swz((aRow0 + mt * 16u) * 128u + kb));
#pragma unroll
            for (int nh = 0; nh < 2; nh++)
                ldsm4(Bf[nh], bcur + swz((bRow0 + nh * 16u) * 128u + kb));
#pragma unroll
            for (int mt = 0; mt < 2; mt++) {
                mma_f16(acc[mt][0], Af[mt], Bf[0][0], Bf[0][2]);
                mma_f16(acc[mt][1], Af[mt], Bf[0][1], Bf[0][3]);
                mma_f16(acc[mt][2], Af[mt], Bf[1][0], Bf[1][2]);
                mma_f16(acc[mt][3], Af[mt], Bf[1][1], Bf[1][3]);
            }
        }
    }

    // ---- epilogue: fp16 partials ----
    const int trow  = lane >> 2;
    const int tcol2 = (lane & 3) * 2;
#pragma unroll
    for (int mt = 0; mt < 2; mt++) {
#pragma unroll
        for (int h = 0; h < 2; h++) {
            const int gr = m0 + wm * 32 + mt * 16 + h * 8 + trow;
#pragma unroll
            for (int nf = 0; nf < 4; nf++) {
                const int gc = n0 + wn * 32 + nf * 8 + tcol2;
                __half2 v;
                v.x = __float2half(acc[mt][nf][h * 2 + 0]);
                v.y = __float2half(acc[mt][nf][h * 2 + 1]);
                *reinterpret_cast<__half2*>(part + (size_t)gr * NHID + gc) = v;
            }
        }
    }
}

// ---------------- unified HMMA fp16 GEMM (gemm1, gemm3, gemm4) ----------------
template <int AM, int BN, bool DUAL>
__global__ __launch_bounds__(512, 1)
void tc_gemm(const __half* __restrict__ Ahi,
             const __half* __restrict__ Alo,
             const __half* __restrict__ Bhi,
             __half* __restrict__ C,
             int ldA, int ldB, int ldC, int nchunk, size_t part_stride)
{
    constexpr int MT = AM / 64;
    constexpr int NH = BN / 64;
    constexpr uint32_t A_B = (uint32_t)AM * 128u;
    constexpr uint32_t B_B = (uint32_t)BN * 128u;
    constexpr uint32_t SS  = (DUAL ? 2u : 1u) * A_B + B_B;   // 48KB all configs
    constexpr int AG = AM * 8;
    constexpr int NG = (DUAL ? 2 : 1) * AG + BN * 8;
    constexpr int NITER = NG / 512;

    extern __shared__ __align__(128) char smem[];
    const uint32_t sbase = smem_u32(smem);
    const int tid  = threadIdx.x;
    const int wid  = tid >> 5;
    const int lane = tid & 31;
    const int wm = wid & 3;
    const int wn = wid >> 2;
    const int m0 = blockIdx.y * AM;
    const int n0 = blockIdx.x * BN;

    const int gz = gridDim.z, bz = blockIdx.z;
    const int cbeg = (nchunk * bz) / gz;
    const int cend = (nchunk * (bz + 1)) / gz;
    C += (size_t)bz * part_stride;

    const char* baseAhi = (const char*)(Ahi + (size_t)m0 * ldA);
    const char* baseAlo = DUAL ? (const char*)(Alo + (size_t)m0 * ldA) : nullptr;
    const char* baseBhi = (const char*)(Bhi + (size_t)n0 * ldB);
    const size_t sA = (size_t)ldA * 2, sB = (size_t)ldB * 2;

    auto load_stage = [&](int c) {
        const uint32_t st = sbase + (uint32_t)(c % 3) * SS;
        const size_t kb = (size_t)c * (BKC * 2);
#pragma unroll
        for (int i = 0; i < NITER; i++) {
            const int idx = tid + i * 512;
            const char* gb;
            uint32_t regoff;
            size_t stride;
            int rr;
            if (idx < AG)                  { rr = idx;      gb = baseAhi; regoff = 0;   stride = sA; }
            else if (DUAL && idx < 2 * AG) { rr = idx - AG; gb = baseAlo; regoff = A_B; stride = sA; }
            else { rr = idx - (DUAL ? 2 : 1) * AG;
                   gb = baseBhi; regoff = (DUAL ? 2u : 1u) * A_B; stride = sB; }
            const int r  = rr >> 3;
            const int cc = rr & 7;
            cp_async16(st + regoff + swz((uint32_t)(r * 128 + cc * 16)),
                       gb + kb + (size_t)r * stride + cc * 16);
        }
        cp_commit();
    };

    const uint32_t rL   = lane & 15;
    const uint32_t cAdd = lane >> 4;
    const uint32_t aRow0 = (uint32_t)(wm * (MT * 16)) + rL;
    const uint32_t bRow0 = (uint32_t)(wn * (NH * 16)) + rL;
    const uint32_t kOff0 = cAdd * 16u;

    float acc[MT][2 * NH][4];
#pragma unroll
    for (int i = 0; i < MT; i++)
#pragma unroll
        for (int j = 0; j < 2 * NH; j++)
#pragma unroll
            for (int k = 0; k < 4; k++) acc[i][j][k] = 0.0f;

    load_stage(cbeg);
    if (cbeg + 1 < cend) load_stage(cbeg + 1);

    for (int c = cbeg; c < cend; c++) {
        if (c + 1 < cend) cp_wait<1>(); else cp_wait<0>();
        __syncthreads();
        if (c + 2 < cend) load_stage(c + 2);

        const uint32_t st   = sbase + (uint32_t)(c % 3) * SS;
        const uint32_t tAhi = st;
        const uint32_t tAlo = st + A_B;
        const uint32_t tBhi = st + (DUAL ? 2u : 1u) * A_B;

#pragma unroll
        for (int ks = 0; ks < 4; ks++) {
            const uint32_t kb = kOff0 + (uint32_t)ks * 32u;
            uint32_t Ah[MT][4], Al[DUAL ? MT : 1][4], Bh[NH][4];
#pragma unroll
            for (int mt = 0; mt < MT; mt++) {
                const uint32_t off = (aRow0 + mt * 16u) * 128u + kb;
                ldsm4(Ah[mt], tAhi + swz(off));
                if (DUAL) ldsm4(Al[mt], tAlo + swz(off));
            }
#pragma unroll
            for (int nh = 0; nh < NH; nh++) {
                const uint32_t off = (bRow0 + nh * 16u) * 128u + kb;
                ldsm4(Bh[nh], tBhi + swz(off));
            }
#pragma unroll
            for (int mt = 0; mt < MT; mt++)
#pragma unroll
                for (int nh = 0; nh < NH; nh++) {
                    mma_f16(acc[mt][2 * nh + 0], Ah[mt], Bh[nh][0], Bh[nh][2]);
                    mma_f16(acc[mt][2 * nh + 1], Ah[mt], Bh[nh][1], Bh[nh][3]);
                    if (DUAL) {
                        mma_f16(acc[mt][2 * nh + 0], Al[mt], Bh[nh][0], Bh[nh][2]);
                        mma_f16(acc[mt][2 * nh + 1], Al[mt], Bh[nh][1], Bh[nh][3]);
                    }
                }
        }
    }

    const int trow  = lane >> 2;
    const int tcol2 = (lane & 3) * 2;
#pragma unroll
    for (int mt = 0; mt < MT; mt++) {
#pragma unroll
        for (int h = 0; h < 2; h++) {
            const int gr = m0 + wm * (MT * 16) + mt * 16 + h * 8 + trow;
#pragma unroll
            for (int nf = 0; nf < 2 * NH; nf++) {
                const int gc = n0 + wn * (NH * 16) + nf * 8 + tcol2;
                __half2 v;
                v.x = __float2half(acc[mt][nf][h * 2 + 0]);
                v.y = __float2half(acc[mt][nf][h * 2 + 1]);
                *reinterpret_cast<__half2*>(C + (size_t)gr * ldC + gc) = v;
            }
        }
    }
}

// ------- reduce for H: Hh = half(relu(sum fp16 parts + b1)) -------
template <int NP>
__global__ void reduce_h_kernel(const __half* __restrict__ part, size_t stride,
                                const float* __restrict__ bias,
                                __half* __restrict__ out)
{
    const int t = blockIdx.x * blockDim.x + threadIdx.x;
    if (t >= MPAD * (NHID / 4)) return;
    const int r = t / (NHID / 4);
    const int c = (t % (NHID / 4)) * 4;
    float4 b = *reinterpret_cast<const float4*>(bias + c);
    float s0 = b.x, s1 = b.y, s2 = b.z, s3 = b.w;
#pragma unroll
    for (int p = 0; p < NP; p++) {
        const __half2* vp = reinterpret_cast<const __half2*>(part + p * stride + (size_t)r * NHID + c);
        const __half2 v0 = vp[0], v1 = vp[1];
        s0 += __half2float(v0.x); s1 += __half2float(v0.y);
        s2 += __half2float(v1.x); s3 += __half2float(v1.y);
    }
    __half2 h0, h1;
    h0.x = __float2half(fmaxf(s0, 0.0f));
    h0.y = __float2half(fmaxf(s1, 0.0f));
    h1.x = __float2half(fmaxf(s2, 0.0f));
    h1.y = __float2half(fmaxf(s3, 0.0f));
    __half2* op = reinterpret_cast<__half2*>(out + (size_t)r * NHID + c);
    op[0] = h0; op[1] = h1;
}

// ------- final reduce: out = sum fp16 parts + bias (fp32 out) -------
template <int NP>
__global__ void reduce_kernel(const __half* __restrict__ part, size_t stride,
                              const float* __restrict__ bias,
                              float* __restrict__ out, int rows, int cols)
{
    const int t = blockIdx.x * blockDim.x + threadIdx.x;
    if (t >= rows * (cols / 4)) return;
    const int r = t / (cols / 4);
    const int c = (t % (cols / 4)) * 4;
    float4 b = *reinterpret_cast<const float4*>(bias + c);
    float s0 = b.x, s1 = b.y, s2 = b.z, s3 = b.w;
#pragma unroll
    for (int p = 0; p < NP; p++) {
        const __half2* vp = reinterpret_cast<const __half2*>(part + p * stride + (size_t)r * cols + c);
        const __half2 v0 = vp[0], v1 = vp[1];
        s0 += __half2float(v0.x); s1 += __half2float(v0.y);
        s2 += __half2float(v1.x); s3 += __half2float(v1.y);
    }
    float4 s; s.x = s0; s.y = s1; s.z = s2; s.w = s3;
    *reinterpret_cast<float4*>(out + (size_t)r * cols + c) = s;
}

// ---------------- x round: fp32 [NROWS,NFEAT] -> fp16 [KPAD,NFEAT] ----------------
__global__ void round_x_kernel(const float* __restrict__ x,
                               __half* __restrict__ xh)
{
    const int t = blockIdx.x * blockDim.x + threadIdx.x;
    if (t >= KPAD * (NFEAT / 4)) return;
    const int r = t / (NFEAT / 4);
    const int c = (t % (NFEAT / 4)) * 4;
    float4 v = make_float4(0.f, 0.f, 0.f, 0.f);
    if (r < NROWS)
        v = *reinterpret_cast<const float4*>(x + (size_t)r * NFEAT + c);
    __half2 H01, H23;
    H01.x = __float2half(v.x); H01.y = __float2half(v.y);
    H23.x = __float2half(v.z); H23.y = __float2half(v.w);
    __half2* hp = reinterpret_cast<__half2*>(xh + (size_t)r * NFEAT + c);
    hp[0] = H01; hp[1] = H23;
}

// ---- generic weight transpose+split: fp32 [R,C] -> fp16 hi/lo [C,R] ----
__global__ void wt_split_kernel(const float* __restrict__ W, int R, int C,
                                __half* __restrict__ hi,
                                __half* __restrict__ lo)
{
    __shared__ float tile[32][33];
    const int tx = threadIdx.x, ty = threadIdx.y;
    const int c0 = blockIdx.x * 32;
    const int k0 = blockIdx.y * 32;
#pragma unroll
    for (int i = 0; i < 4; i++) {
        const int k = k0 + ty + i * 8;
        tile[ty + i * 8][tx] = W[(size_t)k * C + (c0 + tx)];
    }
    __syncthreads();
#pragma unroll
    for (int i = 0; i < 4; i++) {
        const int c = c0 + ty + i * 8;
        const float v = tile[tx][ty + i * 8];
        const __half h = __float2half(v);
        hi[(size_t)c * R + k0 + tx] = h;
        lo[(size_t)c * R + k0 + tx] = __float2half(v - __half2float(h));
    }
}

// ---------------- launcher ----------------
extern "C" void kernel_launch(void* const* d_in, const int* in_sizes, int n_in,
                              void* d_out, int out_size)
{
    const float* x   = (const float*)d_in[0];
    const float* adj = (const float*)d_in[1];
    const float* W1  = (const float*)d_in[2];
    const float* b1  = (const float*)d_in[3];
    const float* W2  = (const float*)d_in[4];
    const float* b2  = (const float*)d_in[5];
    float* out = (float*)d_out;

    __half *part, *Ah, *xh, *W1thi, *W1tlo, *T1t, *Hh, *W2thi, *W2tlo, *T2t;
    cudaGetSymbolAddress((void**)&part, g_part);
    cudaGetSymbolAddress((void**)&Ah,   g_adj_h);
    cudaGetSymbolAddress((void**)&xh,   g_xh);
    cudaGetSymbolAddress((void**)&W1thi, g_W1t_hi);
    cudaGetSymbolAddress((void**)&W1tlo, g_W1t_lo);
    cudaGetSymbolAddress((void**)&T1t,  g_T1t);
    cudaGetSymbolAddress((void**)&Hh,   g_Hh);
    cudaGetSymbolAddress((void**)&W2thi, g_W2t_hi);
    cudaGetSymbolAddress((void**)&W2tlo, g_W2t_lo);
    cudaGetSymbolAddress((void**)&T2t,  g_T2t);

    cudaFuncSetAttribute((const void*)tc_gemm<128, 128, true>,
                         cudaFuncAttributeMaxDynamicSharedMemorySize, TC_SMEM);
    cudaFuncSetAttribute((const void*)tc_gemm<128, 256, false>,
                         cudaFuncAttributeMaxDynamicSharedMemorySize, TC_SMEM);
    cudaFuncSetAttribute((const void*)gemm2_fused,
                         cudaFuncAttributeMaxDynamicSharedMemorySize, F_SMEM);

    // x -> fp16 [KPAD, NFEAT]
    round_x_kernel<<<(KPAD * (NFEAT / 4) + 255) / 256, 256>>>(x, xh);
    // W1^T hi/lo [NHID, NFEAT]
    wt_split_kernel<<<dim3(NHID / 32, NFEAT / 32), dim3(32, 8)>>>(W1, NFEAT, NHID, W1thi, W1tlo);
    // T1t = half((W1t_hi+W1t_lo) @ xh^T) [NHID, KPAD]; K = NFEAT
    tc_gemm<128, 128, true><<<dim3(KPAD / 128, NHID / 128, 1), 512, TC_SMEM>>>(
        W1thi, W1tlo, xh, T1t, NFEAT, NFEAT, KPAD, NFEAT / BKC, 0);
    // fused gemm2: partials + Ah (fp16 adj)
    gemm2_fused<<<dim3(1, MPAD / 128, Z2), 512, F_SMEM>>>(
        adj, T1t, Ah, part, (size_t)MPAD * NHID);
    // Hh = half(relu(sum parts + b1)) [MPAD, NHID]
    reduce_h_kernel<Z2><<<(MPAD * (NHID / 4) + 255) / 256, 256>>>(
        part, (size_t)MPAD * NHID, b1, Hh);
    // W2^T hi/lo [NFEAT, NHID]
    wt_split_kernel<<<dim3(NFEAT / 32, NHID / 32), dim3(32, 8)>>>(W2, NHID, NFEAT, W2thi, W2tlo);
    // T2t = half((W2t_hi+W2t_lo) @ Hh^T) [NFEAT, KPAD]; K = NHID
    tc_gemm<128, 128, true><<<dim3(KPAD / 128, NFEAT / 128, 1), 512, TC_SMEM>>>(
        W2thi, W2tlo, Hh, T2t, NHID, NHID, KPAD, NHID / BKC, 0);
    // gemm4 partials (fp16): part[z] = Ah @ T2t^T  (128x256 tiles, K-split Z4)
    tc_gemm<128, 256, false><<<dim3(NFEAT / 256, KPAD / 128, Z4), 512, TC_SMEM>>>(
        Ah, nullptr, T2t, part, KPAD, KPAD, NFEAT, NCHUNK, (size_t)MPAD * NFEAT);
    // out = sum parts + b2
    reduce_kernel<Z4><<<(NROWS * (NFEAT / 4) + 255) / 256, 256>>>(
        part, (size_t)MPAD * NFEAT, b2, out, NROWS, NFEAT);
}

// round 17
// speedup vs baseline: 1.0332x; 1.0332x over previous
#include <cuda_runtime.h>
#include <cuda_fp16.h>
#include <cstdint>

// ---------------- problem constants ----------------
#define NROWS  10000
#define MPAD   10240           // 80*128
#define NHID   128
#define NFEAT  512
#define KPAD   10112           // 158*64, 79*128
#define BKC    64
#define NCHUNK 157             // ceil(NROWS/64); chunk 157 (k>=10048) is all zero - skipped
#define Z2 11                  // gemm2 K-split
#define Z4 8                   // gemm4 K-split
#define TC_SMEM 147456         // 3 stages x 48KB (template variants)
#define F_SMEM  81920          // fused gemm2: A16 2x16KB + B 3x16KB

// ---------------- scratch (__device__ globals; no allocs) ----------------
__device__ __align__(256) __half g_part[(size_t)Z4 * MPAD * NFEAT];  // fp16 partials (>= Z2*MPAD*NHID)
__device__ __align__(256) __half g_adj_h[(size_t)MPAD * KPAD];       // round16(adj), written by gemm2_fused
__device__ __align__(256) __half g_xh[(size_t)KPAD * NFEAT];         // round16(x), padded rows
__device__ __align__(256) __half g_W1t_hi[NHID * NFEAT];
__device__ __align__(256) __half g_W1t_lo[NHID * NFEAT];
__device__ __align__(256) __half g_T1t[(size_t)NHID * KPAD];         // [NHID, KPAD]
__device__ __align__(256) __half g_Hh [(size_t)MPAD * NHID];         // H fp16 [MPAD, NHID]
__device__ __align__(256) __half g_W2t_hi[NFEAT * NHID];
__device__ __align__(256) __half g_W2t_lo[NFEAT * NHID];
__device__ __align__(256) __half g_T2t[(size_t)NFEAT * KPAD];        // T2^T fp16 [NFEAT, KPAD]

// ---------------- PTX helpers (legal on bare sm_103) ----------------
__device__ __forceinline__ uint32_t smem_u32(const void* p) {
    uint32_t a;
    asm("{ .reg .u64 t; cvta.to.shared.u64 t, %1; cvt.u32.u64 %0, t; }" : "=r"(a) : "l"(p));
    return a;
}
__device__ __forceinline__ uint32_t swz(uint32_t off) {
    return off ^ ((off >> 3) & 0x70);
}
__device__ __forceinline__ void cp_async16(uint32_t dst, const void* src) {
    asm volatile("cp.async.cg.shared.global [%0], [%1], 16;" :: "r"(dst), "l"(src));
}
__device__ __forceinline__ void cp_commit() {
    asm volatile("cp.async.commit_group;" ::: "memory");
}
template <int N>
__device__ __forceinline__ void cp_wait() {
    asm volatile("cp.async.wait_group %0;" :: "n"(N) : "memory");
}
__device__ __forceinline__ void ldsm4(uint32_t* r, uint32_t addr) {
    asm volatile("ldmatrix.sync.aligned.m8n8.x4.shared.b16 {%0,%1,%2,%3}, [%4];"
                 : "=r"(r[0]), "=r"(r[1]), "=r"(r[2]), "=r"(r[3]) : "r"(addr));
}
__device__ __forceinline__ void mma_f16(float* d, const uint32_t* a,
                                        uint32_t b0, uint32_t b1) {
    asm volatile(
        "mma.sync.aligned.m16n8k16.row.col.f32.f16.f16.f32 "
        "{%0,%1,%2,%3}, {%4,%5,%6,%7}, {%8,%9}, {%0,%1,%2,%3};"
        : "+f"(d[0]), "+f"(d[1]), "+f"(d[2]), "+f"(d[3])
        : "r"(a[0]), "r"(a[1]), "r"(a[2]), "r"(a[3]), "r"(b0), "r"(b1));
}
// L2-only fp32 vec4 load (bypass L1)
__device__ __forceinline__ float4 ldg_cg4(const float* p) {
    float4 v;
    asm volatile("ld.global.cg.v4.f32 {%0,%1,%2,%3}, [%4];"
                 : "=f"(v.x), "=f"(v.y), "=f"(v.z), "=f"(v.w) : "l"(p));
    return v;
}
// streaming 8B store (2 x half2)
__device__ __forceinline__ void stg_cs8(void* p, uint32_t a, uint32_t b) {
    asm volatile("st.global.cs.v2.b32 [%0], {%1,%2};" :: "l"(p), "r"(a), "r"(b));
}

// ================= fused gemm2: reads fp32 adj, emits fp16 adj + partials =================
// part[z][m][n] = sum_{k in z} round16(adj)[m][k] * T1t[n][k];  also Ah[m][k] = round16(adj).
// CTA 128x128, 16 warps (4x4), warp tile 32x32, BKC=64.
// A: LDG.cg fp32 (reg-staged, 1-chunk lookahead) -> convert -> STS swizzled fp16 + STG.cs.
// B: cp.async 3-ring.
__global__ __launch_bounds__(512, 1)
void gemm2_fused(const float* __restrict__ adj,
                 const __half* __restrict__ Bhi,   // T1t [NHID, KPAD]
                 __half* __restrict__ Ah,          // [MPAD, KPAD]
                 __half* __restrict__ part, size_t part_stride)
{
    extern __shared__ __align__(128) char smem[];
    const uint32_t sbase = smem_u32(smem);
    const uint32_t A16b  = sbase;            // 2 x 16KB
    const uint32_t Bb    = sbase + 32768u;   // 3 x 16KB
    const int tid  = threadIdx.x;
    const int wid  = tid >> 5;
    const int lane = tid & 31;
    const int wm = wid & 3;
    const int wn = wid >> 2;
    const int m0 = blockIdx.y * 128;
    const int n0 = blockIdx.x * 128;

    const int gz = gridDim.z, bz = blockIdx.z;
    const int cbeg = (NCHUNK * bz) / gz;
    const int cend = (NCHUNK * (bz + 1)) / gz;
    part += (size_t)bz * part_stride;

    const __half* baseB = Bhi + (size_t)n0 * KPAD;

    auto loadB = [&](int c) {
        const size_t kb = (size_t)c * 128;   // bytes along K
        const uint32_t slot = Bb + (uint32_t)(c % 3) * 16384u;
#pragma unroll
        for (int i = 0; i < 2; i++) {
            const int idx = tid + i * 512;   // 0..1023
            const int r  = idx >> 3;
            const int cc = idx & 7;
            cp_async16(slot + swz((uint32_t)(r * 128 + cc * 16)),
                       (const char*)baseB + kb + (size_t)r * (KPAD * 2) + cc * 16);
        }
        cp_commit();
    };

    auto loadA = [&](int c, float4* v) {
#pragma unroll
        for (int j = 0; j < 4; j++) {
            const int idx = tid + j * 512;
            const int row = idx >> 4;
            const int g   = idx & 15;
            const int gr  = m0 + row;
            const int gk  = c * 64 + g * 4;
            if (gr < NROWS && gk < NROWS)
                v[j] = ldg_cg4(adj + (size_t)gr * NROWS + gk);
            else
                v[j] = make_float4(0.f, 0.f, 0.f, 0.f);
        }
    };

    const uint32_t rL   = lane & 15;
    const uint32_t cAdd = lane >> 4;
    const uint32_t aRow0 = (uint32_t)(wm * 32) + rL;
    const uint32_t bRow0 = (uint32_t)(wn * 32) + rL;
    const uint32_t kOff0 = cAdd * 16u;

    float acc[2][4][4];
#pragma unroll
    for (int i = 0; i < 2; i++)
#pragma unroll
        for (int j = 0; j < 4; j++)
#pragma unroll
            for (int k = 0; k < 4; k++) acc[i][j][k] = 0.0f;

    // prologue
    float4 vreg[4];
    loadA(cbeg, vreg);
    loadB(cbeg);
    if (cbeg + 1 < cend) loadB(cbeg + 1);
    if (cbeg + 2 < cend) loadB(cbeg + 2);

    for (int c = cbeg; c < cend; c++) {
        // ---- convert + store A (regs hold chunk c) ----
        const uint32_t a16cur = A16b + (uint32_t)(c & 1) * 16384u;
#pragma unroll
        for (int j = 0; j < 4; j++) {
            const int idx = tid + j * 512;
            const int row = idx >> 4;
            const int g   = idx & 15;
            __half2 p0 = __floats2half2_rn(vreg[j].x, vreg[j].y);
            __half2 p1 = __floats2half2_rn(vreg[j].z, vreg[j].w);
            const uint32_t soff = swz((uint32_t)(row * 128 + (g >> 1) * 16)) + (uint32_t)(g & 1) * 8u;
            __half2* sp = reinterpret_cast<__half2*>(smem + (a16cur - sbase) + soff);
            sp[0] = p0; sp[1] = p1;
            stg_cs8(Ah + (size_t)(m0 + row) * KPAD + c * 64 + g * 4,
                    *reinterpret_cast<uint32_t*>(&p0), *reinterpret_cast<uint32_t*>(&p1));
        }
        __syncthreads();                       // A16[c] visible

        if (c + 1 < cend) loadA(c + 1, vreg);  // refill regs (consumed next iter)

        const int rem = cend - 1 - c;
        if (rem >= 2)      cp_wait<2>();
        else if (rem == 1) cp_wait<1>();
        else               cp_wait<0>();

        const uint32_t bcur = Bb + (uint32_t)(c % 3) * 16384u;
#pragma unroll
        for (int ks = 0; ks < 4; ks++) {
            const uint32_t kb = kOff0 + (uint32_t)ks * 32u;
            uint32_t Af[2][4], Bf[2][4];
#pragma unroll
            for (int mt = 0; mt < 2; mt++)
                ldsm4(Af[mt], a16cur + swz((aRow0 + mt * 16u) * 128u + kb));
#pragma unroll
            for (int nh = 0; nh < 2; nh++)
                ldsm4(Bf[nh], bcur + swz((bRow0 + nh * 16u) * 128u + kb));
#pragma unroll
            for (int mt = 0; mt < 2; mt++) {
                mma_f16(acc[mt][0], Af[mt], Bf[0][0], Bf[0][2]);
                mma_f16(acc[mt][1], Af[mt], Bf[0][1], Bf[0][3]);
                mma_f16(acc[mt][2], Af[mt], Bf[1][0], Bf[1][2]);
                mma_f16(acc[mt][3], Af[mt], Bf[1][1], Bf[1][3]);
            }
        }
        __syncthreads();                       // all warps done reading B[c%3]
        if (c + 3 < cend) loadB(c + 3);        // reuse slot c%3
    }

    // ---- epilogue: fp16 partials ----
    const int trow  = lane >> 2;
    const int tcol2 = (lane & 3) * 2;
#pragma unroll
    for (int mt = 0; mt < 2; mt++) {
#pragma unroll
        for (int h = 0; h < 2; h++) {
            const int gr = m0 + wm * 32 + mt * 16 + h * 8 + trow;
#pragma unroll
            for (int nf = 0; nf < 4; nf++) {
                const int gc = n0 + wn * 32 + nf * 8 + tcol2;
                __half2 v;
                v.x = __float2half(acc[mt][nf][h * 2 + 0]);
                v.y = __float2half(acc[mt][nf][h * 2 + 1]);
                *reinterpret_cast<__half2*>(part + (size_t)gr * NHID + gc) = v;
            }
        }
    }
}

// ---------------- unified HMMA fp16 GEMM (gemm1, gemm3, gemm4) ----------------
template <int AM, int BN, bool DUAL>
__global__ __launch_bounds__(512, 1)
void tc_gemm(const __half* __restrict__ Ahi,
             const __half* __restrict__ Alo,
             const __half* __restrict__ Bhi,
             __half* __restrict__ C,
             int ldA, int ldB, int ldC, int nchunk, size_t part_stride)
{
    constexpr int MT = AM / 64;
    constexpr int NH = BN / 64;
    constexpr uint32_t A_B = (uint32_t)AM * 128u;
    constexpr uint32_t B_B = (uint32_t)BN * 128u;
    constexpr uint32_t SS  = (DUAL ? 2u : 1u) * A_B + B_B;   // 48KB all configs
    constexpr int AG = AM * 8;
    constexpr int NG = (DUAL ? 2 : 1) * AG + BN * 8;
    constexpr int NITER = NG / 512;

    extern __shared__ __align__(128) char smem[];
    const uint32_t sbase = smem_u32(smem);
    const int tid  = threadIdx.x;
    const int wid  = tid >> 5;
    const int lane = tid & 31;
    const int wm = wid & 3;
    const int wn = wid >> 2;
    const int m0 = blockIdx.y * AM;
    const int n0 = blockIdx.x * BN;

    const int gz = gridDim.z, bz = blockIdx.z;
    const int cbeg = (nchunk * bz) / gz;
    const int cend = (nchunk * (bz + 1)) / gz;
    C += (size_t)bz * part_stride;

    const char* baseAhi = (const char*)(Ahi + (size_t)m0 * ldA);
    const char* baseAlo = DUAL ? (const char*)(Alo + (size_t)m0 * ldA) : nullptr;
    const char* baseBhi = (const char*)(Bhi + (size_t)n0 * ldB);
    const size_t sA = (size_t)ldA * 2, sB = (size_t)ldB * 2;

    auto load_stage = [&](int c) {
        const uint32_t st = sbase + (uint32_t)(c % 3) * SS;
        const size_t kb = (size_t)c * (BKC * 2);
#pragma unroll
        for (int i = 0; i < NITER; i++) {
            const int idx = tid + i * 512;
            const char* gb;
            uint32_t regoff;
            size_t stride;
            int rr;
            if (idx < AG)                  { rr = idx;      gb = baseAhi; regoff = 0;   stride = sA; }
            else if (DUAL && idx < 2 * AG) { rr = idx - AG; gb = baseAlo; regoff = A_B; stride = sA; }
            else { rr = idx - (DUAL ? 2 : 1) * AG;
                   gb = baseBhi; regoff = (DUAL ? 2u : 1u) * A_B; stride = sB; }
            const int r  = rr >> 3;
            const int cc = rr & 7;
            cp_async16(st + regoff + swz((uint32_t)(r * 128 + cc * 16)),
                       gb + kb + (size_t)r * stride + cc * 16);
        }
        cp_commit();
    };

    const uint32_t rL   = lane & 15;
    const uint32_t cAdd = lane >> 4;
    const uint32_t aRow0 = (uint32_t)(wm * (MT * 16)) + rL;
    const uint32_t bRow0 = (uint32_t)(wn * (NH * 16)) + rL;
    const uint32_t kOff0 = cAdd * 16u;

    float acc[MT][2 * NH][4];
#pragma unroll
    for (int i = 0; i < MT; i++)
#pragma unroll
        for (int j = 0; j < 2 * NH; j++)
#pragma unroll
            for (int k = 0; k < 4; k++) acc[i][j][k] = 0.0f;

    load_stage(cbeg);
    if (cbeg + 1 < cend) load_stage(cbeg + 1);

    for (int c = cbeg; c < cend; c++) {
        if (c + 1 < cend) cp_wait<1>(); else cp_wait<0>();
        __syncthreads();
        if (c + 2 < cend) load_stage(c + 2);

        const uint32_t st   = sbase + (uint32_t)(c % 3) * SS;
        const uint32_t tAhi = st;
        const uint32_t tAlo = st + A_B;
        const uint32_t tBhi = st + (DUAL ? 2u : 1u) * A_B;

#pragma unroll
        for (int ks = 0; ks < 4; ks++) {
            const uint32_t kb = kOff0 + (uint32_t)ks * 32u;
            uint32_t Ah[MT][4], Al[DUAL ? MT : 1][4], Bh[NH][4];
#pragma unroll
            for (int mt = 0; mt < MT; mt++) {
                const uint32_t off = (aRow0 + mt * 16u) * 128u + kb;
                ldsm4(Ah[mt], tAhi + swz(off));
                if (DUAL) ldsm4(Al[mt], tAlo + swz(off));
            }
#pragma unroll
            for (int nh = 0; nh < NH; nh++) {
                const uint32_t off = (bRow0 + nh * 16u) * 128u + kb;
                ldsm4(Bh[nh], tBhi + swz(off));
            }
#pragma unroll
            for (int mt = 0; mt < MT; mt++)
#pragma unroll
                for (int nh = 0; nh < NH; nh++) {
                    mma_f16(acc[mt][2 * nh + 0], Ah[mt], Bh[nh][0], Bh[nh][2]);
                    mma_f16(acc[mt][2 * nh + 1], Ah[mt], Bh[nh][1], Bh[nh][3]);
                    if (DUAL) {
                        mma_f16(acc[mt][2 * nh + 0], Al[mt], Bh[nh][0], Bh[nh][2]);
                        mma_f16(acc[mt][2 * nh + 1], Al[mt], Bh[nh][1], Bh[nh][3]);
                    }
                }
        }
    }

    const int trow  = lane >> 2;
    const int tcol2 = (lane & 3) * 2;
#pragma unroll
    for (int mt = 0; mt < MT; mt++) {
#pragma unroll
        for (int h = 0; h < 2; h++) {
            const int gr = m0 + wm * (MT * 16) + mt * 16 + h * 8 + trow;
#pragma unroll
            for (int nf = 0; nf < 2 * NH; nf++) {
                const int gc = n0 + wn * (NH * 16) + nf * 8 + tcol2;
                __half2 v;
                v.x = __float2half(acc[mt][nf][h * 2 + 0]);
                v.y = __float2half(acc[mt][nf][h * 2 + 1]);
                *reinterpret_cast<__half2*>(C + (size_t)gr * ldC + gc) = v;
            }
        }
    }
}

// ------- reduce for H: Hh = half(relu(sum fp16 parts + b1)) -------
template <int NP>
__global__ void reduce_h_kernel(const __half* __restrict__ part, size_t stride,
                                const float* __restrict__ bias,
                                __half* __restrict__ out)
{
    const int t = blockIdx.x * blockDim.x + threadIdx.x;
    if (t >= MPAD * (NHID / 4)) return;
    const int r = t / (NHID / 4);
    const int c = (t % (NHID / 4)) * 4;
    float4 b = *reinterpret_cast<const float4*>(bias + c);
    float s0 = b.x, s1 = b.y, s2 = b.z, s3 = b.w;
#pragma unroll
    for (int p = 0; p < NP; p++) {
        const __half2* vp = reinterpret_cast<const __half2*>(part + p * stride + (size_t)r * NHID + c);
        const __half2 v0 = vp[0], v1 = vp[1];
        s0 += __half2float(v0.x); s1 += __half2float(v0.y);
        s2 += __half2float(v1.x); s3 += __half2float(v1.y);
    }
    __half2 h0, h1;
    h0.x = __float2half(fmaxf(s0, 0.0f));
    h0.y = __float2half(fmaxf(s1, 0.0f));
    h1.x = __float2half(fmaxf(s2, 0.0f));
    h1.y = __float2half(fmaxf(s3, 0.0f));
    __half2* op = reinterpret_cast<__half2*>(out + (size_t)r * NHID + c);
    op[0] = h0; op[1] = h1;
}

// ------- final reduce: out = sum fp16 parts + bias (fp32 out) -------
template <int NP>
__global__ void reduce_kernel(const __half* __restrict__ part, size_t stride,
                              const float* __restrict__ bias,
                              float* __restrict__ out, int rows, int cols)
{
    const int t = blockIdx.x * blockDim.x + threadIdx.x;
    if (t >= rows * (cols / 4)) return;
    const int r = t / (cols / 4);
    const int c = (t % (cols / 4)) * 4;
    float4 b = *reinterpret_cast<const float4*>(bias + c);
    float s0 = b.x, s1 = b.y, s2 = b.z, s3 = b.w;
#pragma unroll
    for (int p = 0; p < NP; p++) {
        const __half2* vp = reinterpret_cast<const __half2*>(part + p * stride + (size_t)r * cols + c);
        const __half2 v0 = vp[0], v1 = vp[1];
        s0 += __half2float(v0.x); s1 += __half2float(v0.y);
        s2 += __half2float(v1.x); s3 += __half2float(v1.y);
    }
    float4 s; s.x = s0; s.y = s1; s.z = s2; s.w = s3;
    *reinterpret_cast<float4*>(out + (size_t)r * cols + c) = s;
}

// ---------------- x round: fp32 [NROWS,NFEAT] -> fp16 [KPAD,NFEAT] ----------------
__global__ void round_x_kernel(const float* __restrict__ x,
                               __half* __restrict__ xh)
{
    const int t = blockIdx.x * blockDim.x + threadIdx.x;
    if (t >= KPAD * (NFEAT / 4)) return;
    const int r = t / (NFEAT / 4);
    const int c = (t % (NFEAT / 4)) * 4;
    float4 v = make_float4(0.f, 0.f, 0.f, 0.f);
    if (r < NROWS)
        v = *reinterpret_cast<const float4*>(x + (size_t)r * NFEAT + c);
    __half2 H01, H23;
    H01.x = __float2half(v.x); H01.y = __float2half(v.y);
    H23.x = __float2half(v.z); H23.y = __float2half(v.w);
    __half2* hp = reinterpret_cast<__half2*>(xh + (size_t)r * NFEAT + c);
    hp[0] = H01; hp[1] = H23;
}

// ---- generic weight transpose+split: fp32 [R,C] -> fp16 hi/lo [C,R] ----
__global__ void wt_split_kernel(const float* __restrict__ W, int R, int C,
                                __half* __restrict__ hi,
                                __half* __restrict__ lo)
{
    __shared__ float tile[32][33];
    const int tx = threadIdx.x, ty = threadIdx.y;
    const int c0 = blockIdx.x * 32;
    const int k0 = blockIdx.y * 32;
#pragma unroll
    for (int i = 0; i < 4; i++) {
        const int k = k0 + ty + i * 8;
        tile[ty + i * 8][tx] = W[(size_t)k * C + (c0 + tx)];
    }
    __syncthreads();
#pragma unroll
    for (int i = 0; i < 4; i++) {
        const int c = c0 + ty + i * 8;
        const float v = tile[tx][ty + i * 8];
        const __half h = __float2half(v);
        hi[(size_t)c * R + k0 + tx] = h;
        lo[(size_t)c * R + k0 + tx] = __float2half(v - __half2float(h));
    }
}

// ---------------- launcher ----------------
extern "C" void kernel_launch(void* const* d_in, const int* in_sizes, int n_in,
                              void* d_out, int out_size)
{
    const float* x   = (const float*)d_in[0];
    const float* adj = (const float*)d_in[1];
    const float* W1  = (const float*)d_in[2];
    const float* b1  = (const float*)d_in[3];
    const float* W2  = (const float*)d_in[4];
    const float* b2  = (const float*)d_in[5];
    float* out = (float*)d_out;

    __half *part, *Ah, *xh, *W1thi, *W1tlo, *T1t, *Hh, *W2thi, *W2tlo, *T2t;
    cudaGetSymbolAddress((void**)&part, g_part);
    cudaGetSymbolAddress((void**)&Ah,   g_adj_h);
    cudaGetSymbolAddress((void**)&xh,   g_xh);
    cudaGetSymbolAddress((void**)&W1thi, g_W1t_hi);
    cudaGetSymbolAddress((void**)&W1tlo, g_W1t_lo);
    cudaGetSymbolAddress((void**)&T1t,  g_T1t);
    cudaGetSymbolAddress((void**)&Hh,   g_Hh);
    cudaGetSymbolAddress((void**)&W2thi, g_W2t_hi);
    cudaGetSymbolAddress((void**)&W2tlo, g_W2t_lo);
    cudaGetSymbolAddress((void**)&T2t,  g_T2t);

    cudaFuncSetAttribute((const void*)tc_gemm<128, 128, true>,
                         cudaFuncAttributeMaxDynamicSharedMemorySize, TC_SMEM);
    cudaFuncSetAttribute((const void*)tc_gemm<128, 256, false>,
                         cudaFuncAttributeMaxDynamicSharedMemorySize, TC_SMEM);
    cudaFuncSetAttribute((const void*)gemm2_fused,
                         cudaFuncAttributeMaxDynamicSharedMemorySize, F_SMEM);

    // x -> fp16 [KPAD, NFEAT]
    round_x_kernel<<<(KPAD * (NFEAT / 4) + 255) / 256, 256>>>(x, xh);
    // W1^T hi/lo [NHID, NFEAT]
    wt_split_kernel<<<dim3(NHID / 32, NFEAT / 32), dim3(32, 8)>>>(W1, NFEAT, NHID, W1thi, W1tlo);
    // T1t = half((W1t_hi+W1t_lo) @ xh^T) [NHID, KPAD]; K = NFEAT
    tc_gemm<128, 128, true><<<dim3(KPAD / 128, NHID / 128, 1), 512, TC_SMEM>>>(
        W1thi, W1tlo, xh, T1t, NFEAT, NFEAT, KPAD, NFEAT / BKC, 0);
    // fused gemm2: partials + Ah (fp16 adj); skips all-zero chunk 157
    gemm2_fused<<<dim3(1, MPAD / 128, Z2), 512, F_SMEM>>>(
        adj, T1t, Ah, part, (size_t)MPAD * NHID);
    // Hh = half(relu(sum parts + b1)) [MPAD, NHID]
    reduce_h_kernel<Z2><<<(MPAD * (NHID / 4) + 255) / 256, 256>>>(
        part, (size_t)MPAD * NHID, b1, Hh);
    // W2^T hi/lo [NFEAT, NHID]
    wt_split_kernel<<<dim3(NFEAT / 32, NHID / 32), dim3(32, 8)>>>(W2, NHID, NFEAT, W2thi, W2tlo);
    // T2t = half((W2t_hi+W2t_lo) @ Hh^T) [NFEAT, KPAD]; K = NHID
    tc_gemm<128, 128, true><<<dim3(KPAD / 128, NFEAT / 128, 1), 512, TC_SMEM>>>(
        W2thi, W2tlo, Hh, T2t, NHID, NHID, KPAD, NHID / BKC, 0);
    // gemm4 partials (fp16): part[z] = Ah @ T2t^T  (128x256 tiles, K-split Z4, 157 chunks)
    tc_gemm<128, 256, false><<<dim3(NFEAT / 256, KPAD / 128, Z4), 512, TC_SMEM>>>(
        Ah, nullptr, T2t, part, KPAD, KPAD, NFEAT, NCHUNK, (size_t)MPAD * NFEAT);
    // out = sum parts + b2
    reduce_kernel<Z4><<<(NROWS * (NFEAT / 4) + 255) / 256, 256>>>(
        part, (size_t)MPAD * NFEAT, b2, out, NROWS, NFEAT);
}